// round 8
// baseline (speedup 1.0000x reference)
#include <cuda_runtime.h>
#include <cuda_bf16.h>
#include <cstdint>
#include <cstddef>

#define NMAX 98304
#define EMAX 786432
#define BMAX 512

__device__ float g_h   [(size_t)NMAX * 128];
__device__ float g_eenc[(size_t)EMAX * 64];
__device__ float g_eMR [(size_t)EMAX * 512];
__device__ __nv_bfloat16 g_ABh [(size_t)NMAX * 1024];
__device__ __nv_bfloat16 g_eMc [(size_t)EMAX * 256];
__device__ __nv_bfloat16 g_eRc [(size_t)EMAX * 256];
__device__ float g_aggH[(size_t)NMAX * 512];
__device__ float g_cat [(size_t)NMAX * 256];
__device__ float g_hid [(size_t)NMAX * 256];
__device__ float g_t   [(size_t)BMAX * 2 * 128 * 128];
__device__ float g_stk [(size_t)BMAX * 2 * 128 * 128];
__device__ float g_la  [(size_t)BMAX * 128 * 128];
__device__ float g_W1cat[128 * 1024];
__device__ float g_W2cat[512 * 128];
__device__ float g_Wecat[64 * 512];
__device__ float g_becat[512];
__device__ int   g_sizes [2 * BMAX];
__device__ int   g_starts[2 * BMAX + 1];
__device__ int   g_din [NMAX];
__device__ int   g_dout[NMAX];
__device__ int   g_pin [NMAX + 1];
__device__ int   g_pout[NMAX + 1];
__device__ int   g_cin [NMAX];
__device__ int   g_cout[NMAX];
__device__ int   g_iin [EMAX];
__device__ int   g_iout[EMAX];
__device__ int   g_oin [EMAX];
__device__ int   g_oout[EMAX];

__device__ __forceinline__ float warp_max(float v) {
    #pragma unroll
    for (int o = 16; o; o >>= 1) v = fmaxf(v, __shfl_xor_sync(0xffffffffu, v, o));
    return v;
}
__device__ __forceinline__ float warp_sum(float v) {
    #pragma unroll
    for (int o = 16; o; o >>= 1) v += __shfl_xor_sync(0xffffffffu, v, o);
    return v;
}
__device__ __forceinline__ uint32_t f2tf32(float x) {
    uint32_t r;
    asm("cvt.rna.tf32.f32 %0, %1;" : "=r"(r) : "f"(x));
    return r;
}
__device__ __forceinline__ uint32_t pkbf(float x, float y) {
    __nv_bfloat162 h = __floats2bfloat162_rn(x, y);
    return *(uint32_t*)&h;
}
__device__ __forceinline__ void mma_tf32(float* d, const uint32_t* a, const uint32_t* b) {
    asm volatile(
        "mma.sync.aligned.m16n8k8.row.col.f32.tf32.tf32.f32 "
        "{%0,%1,%2,%3}, {%4,%5,%6,%7}, {%8,%9}, {%0,%1,%2,%3};"
        : "+f"(d[0]), "+f"(d[1]), "+f"(d[2]), "+f"(d[3])
        : "r"(a[0]), "r"(a[1]), "r"(a[2]), "r"(a[3]), "r"(b[0]), "r"(b[1]));
}
__device__ __forceinline__ void mma_bf16(float* d, const uint32_t* a, const uint32_t* b) {
    asm volatile(
        "mma.sync.aligned.m16n8k16.row.col.f32.bf16.bf16.f32 "
        "{%0,%1,%2,%3}, {%4,%5,%6,%7}, {%8,%9}, {%0,%1,%2,%3};"
        : "+f"(d[0]), "+f"(d[1]), "+f"(d[2]), "+f"(d[3])
        : "r"(a[0]), "r"(a[1]), "r"(a[2]), "r"(a[3]), "r"(b[0]), "r"(b[1]));
}
__device__ __forceinline__ void store2(float v0, float v1, float* p) {
    p[0] = v0; p[1] = v1;
}
__device__ __forceinline__ void store2(float v0, float v1, __nv_bfloat16* p) {
    *(__nv_bfloat162*)p = __floats2bfloat162_rn(v0, v1);
}

__global__ void zero_f(float* p, size_t n) {
    for (size_t i = (size_t)blockIdx.x * 256 + threadIdx.x; i < n;
         i += (size_t)gridDim.x * 256) p[i] = 0.f;
}
__global__ void zero_i(int* p, int n) {
    int i = blockIdx.x * 256 + threadIdx.x;
    if (i < n) p[i] = 0;
}
__global__ void copy_i(const int* a, int* b, int n) {
    int i = blockIdx.x * 256 + threadIdx.x;
    if (i < n) b[i] = a[i];
}

// ---------------------------------------------------------------------------
// tf32 GEMM, BM=128 BN=64, 8 warps (4M x 2N), warp tile 32x32 -> 32 acc regs.
// Double-buffered smem. EPI: 0=store 1=+bias 2=relu(+bias) 3=C+=v+bias
// ---------------------------------------------------------------------------
template <int EPI, typename OutT>
__global__ __launch_bounds__(256) void gemm_tf32(
    const float* __restrict__ A, int lda, const float* __restrict__ W, int ldb,
    OutT* __restrict__ C, int ldc, const float* __restrict__ bias, int K)
{
    constexpr int BM = 128, BN = 64, BK = 16;
    __shared__ uint2    As2[2][2][BM][4];
    __shared__ uint32_t Bs[2][BK][BN + 8];
    const int row0 = blockIdx.y * BM, col0 = blockIdx.x * BN;
    const int t = threadIdx.x, lane = t & 31, warp = t >> 5;
    const int wm = (warp & 3) * 32;
    const int wn = (warp >> 2) * 32;
    const int g = lane >> 2, c = lane & 3;
    const int am = t >> 1, aks = t & 1;
    const int bk = t >> 4, bnq = (t & 15) * 4;

    float acc[2][4][4];
    #pragma unroll
    for (int mi = 0; mi < 2; ++mi)
        #pragma unroll
        for (int ni = 0; ni < 4; ++ni)
            #pragma unroll
            for (int j = 0; j < 4; ++j) acc[mi][ni][j] = 0.f;

    float4 ra0, ra1, rb;

    auto gload = [&](int k0) {
        const float* ap = &A[(size_t)(row0 + am) * lda + k0 + aks * 8];
        ra0 = *(const float4*)(ap);
        ra1 = *(const float4*)(ap + 4);
        rb = *(const float4*)&W[(size_t)(k0 + bk) * ldb + col0 + bnq];
    };
    auto sstore = [&](int p) {
        As2[p][aks][am][0] = make_uint2(f2tf32(ra0.x), f2tf32(ra1.x));
        As2[p][aks][am][1] = make_uint2(f2tf32(ra0.y), f2tf32(ra1.y));
        As2[p][aks][am][2] = make_uint2(f2tf32(ra0.z), f2tf32(ra1.z));
        As2[p][aks][am][3] = make_uint2(f2tf32(ra0.w), f2tf32(ra1.w));
        uint32_t* dst = &Bs[p][bk][bnq];
        dst[0] = f2tf32(rb.x); dst[1] = f2tf32(rb.y);
        dst[2] = f2tf32(rb.z); dst[3] = f2tf32(rb.w);
    };
    auto scompute = [&](int p) {
        #pragma unroll
        for (int ks = 0; ks < 2; ++ks) {
            const int kb = ks * 8;
            uint32_t af[2][4];
            #pragma unroll
            for (int mi = 0; mi < 2; ++mi) {
                int m = wm + mi * 16;
                uint2 u0 = As2[p][ks][m + g][c];
                uint2 u1 = As2[p][ks][m + g + 8][c];
                af[mi][0] = u0.x; af[mi][1] = u1.x;
                af[mi][2] = u0.y; af[mi][3] = u1.y;
            }
            uint32_t bf[4][2];
            #pragma unroll
            for (int ni = 0; ni < 4; ++ni) {
                int n = wn + ni * 8 + g;
                bf[ni][0] = Bs[p][kb + c][n];
                bf[ni][1] = Bs[p][kb + c + 4][n];
            }
            #pragma unroll
            for (int mi = 0; mi < 2; ++mi)
                #pragma unroll
                for (int ni = 0; ni < 4; ++ni)
                    mma_tf32(acc[mi][ni], af[mi], bf[ni]);
        }
    };

    gload(0);
    sstore(0);
    __syncthreads();
    int p = 0;
    for (int k0 = 0; k0 < K; k0 += BK) {
        const bool more = (k0 + BK < K);
        if (more) gload(k0 + BK);
        scompute(p);
        if (more) sstore(p ^ 1);
        __syncthreads();
        p ^= 1;
    }
    #pragma unroll
    for (int mi = 0; mi < 2; ++mi) {
        #pragma unroll
        for (int ni = 0; ni < 4; ++ni) {
            int row = row0 + wm + mi * 16 + g;
            int col = col0 + wn + ni * 8 + 2 * c;
            #pragma unroll
            for (int half = 0; half < 2; ++half) {
                int r = row + half * 8;
                float v0 = acc[mi][ni][2 * half + 0];
                float v1 = acc[mi][ni][2 * half + 1];
                if (EPI >= 1) { v0 += bias[col]; v1 += bias[col + 1]; }
                if (EPI == 2) { v0 = fmaxf(v0, 0.f); v1 = fmaxf(v1, 0.f); }
                size_t off = (size_t)r * ldc + col;
                if (EPI == 3) { C[off] += v0; C[off + 1] += v1; }
                else          store2(v0, v1, &C[off]);
            }
        }
    }
}

// ---------------------------------------------------------------------------
// bf16 m16n8k16 GEMM, BM=128 BN=64, warp tile 32x32 (for the ABp GEMM).
// ---------------------------------------------------------------------------
template <int EPI, typename OutT>
__global__ __launch_bounds__(256) void gemm_bf16k(
    const float* __restrict__ A, int lda, const float* __restrict__ W, int ldb,
    OutT* __restrict__ C, int ldc, const float* __restrict__ bias, int K)
{
    constexpr int BM = 128, BN = 64, BK = 16;
    __shared__ uint2 As2[2][BM][5];
    __shared__ uint2 Bs2[2][BN][5];
    const int row0 = blockIdx.y * BM, col0 = blockIdx.x * BN;
    const int t = threadIdx.x, lane = t & 31, warp = t >> 5;
    const int wm = (warp & 3) * 32;
    const int wn = (warp >> 2) * 32;
    const int g = lane >> 2, c = lane & 3;
    const int am = t >> 1, ah = t & 1;
    const int bn = t & 63, bc = t >> 6;   // one slot per thread: n = bn, c = bc

    float acc[2][4][4];
    #pragma unroll
    for (int mi = 0; mi < 2; ++mi)
        #pragma unroll
        for (int ni = 0; ni < 4; ++ni)
            #pragma unroll
            for (int j = 0; j < 4; ++j) acc[mi][ni][j] = 0.f;

    float4 ra0, ra1;
    float w0, w1, w2, w3;

    auto gload = [&](int k0) {
        const float* ap = &A[(size_t)(row0 + am) * lda + k0 + 4 * ah];
        ra0 = *(const float4*)(ap);
        ra1 = *(const float4*)(ap + 8);
        const float* wp = &W[(size_t)(k0 + 2 * bc) * ldb + col0 + bn];
        w0 = wp[0];
        w1 = wp[ldb];
        w2 = wp[8 * (size_t)ldb];
        w3 = wp[9 * (size_t)ldb];
    };
    auto sstore = [&](int p) {
        As2[p][am][2 * ah]     = make_uint2(pkbf(ra0.x, ra0.y), pkbf(ra1.x, ra1.y));
        As2[p][am][2 * ah + 1] = make_uint2(pkbf(ra0.z, ra0.w), pkbf(ra1.z, ra1.w));
        Bs2[p][bn][bc] = make_uint2(pkbf(w0, w1), pkbf(w2, w3));
    };
    auto scompute = [&](int p) {
        uint32_t af[2][4];
        #pragma unroll
        for (int mi = 0; mi < 2; ++mi) {
            int m = wm + mi * 16;
            uint2 u0 = As2[p][m + g][c];
            uint2 u1 = As2[p][m + g + 8][c];
            af[mi][0] = u0.x; af[mi][1] = u1.x;
            af[mi][2] = u0.y; af[mi][3] = u1.y;
        }
        uint32_t bf[4][2];
        #pragma unroll
        for (int ni = 0; ni < 4; ++ni) {
            uint2 v = Bs2[p][wn + ni * 8 + g][c];
            bf[ni][0] = v.x; bf[ni][1] = v.y;
        }
        #pragma unroll
        for (int mi = 0; mi < 2; ++mi)
            #pragma unroll
            for (int ni = 0; ni < 4; ++ni)
                mma_bf16(acc[mi][ni], af[mi], bf[ni]);
    };

    gload(0);
    sstore(0);
    __syncthreads();
    int p = 0;
    for (int k0 = 0; k0 < K; k0 += BK) {
        const bool more = (k0 + BK < K);
        if (more) gload(k0 + BK);
        scompute(p);
        if (more) sstore(p ^ 1);
        __syncthreads();
        p ^= 1;
    }
    #pragma unroll
    for (int mi = 0; mi < 2; ++mi) {
        #pragma unroll
        for (int ni = 0; ni < 4; ++ni) {
            int row = row0 + wm + mi * 16 + g;
            int col = col0 + wn + ni * 8 + 2 * c;
            #pragma unroll
            for (int half = 0; half < 2; ++half) {
                int r = row + half * 8;
                float v0 = acc[mi][ni][2 * half + 0];
                float v1 = acc[mi][ni][2 * half + 1];
                if (EPI >= 1) { v0 += bias[col]; v1 += bias[col + 1]; }
                if (EPI == 2) { v0 = fmaxf(v0, 0.f); v1 = fmaxf(v1, 0.f); }
                size_t off = (size_t)r * ldc + col;
                if (EPI == 3) { C[off] += v0; C[off + 1] += v1; }
                else          store2(v0, v1, &C[off]);
            }
        }
    }
}

__global__ void pack_w1cat(const float* __restrict__ m1, const float* __restrict__ r1,
                           float* __restrict__ w) {
    int i = blockIdx.x * 256 + threadIdx.x;
    if (i >= 128 * 1024) return;
    int k = i >> 10, j = i & 1023;
    float v;
    if (j < 256)      v = m1[k * 256 + j];
    else if (j < 512) v = m1[(128 + k) * 256 + (j - 256)];
    else if (j < 768) v = r1[k * 256 + (j - 512)];
    else              v = r1[(128 + k) * 256 + (j - 768)];
    w[i] = v;
}
__global__ void pack_w2cat(const float* __restrict__ m2, const float* __restrict__ r2,
                           float* __restrict__ w) {
    int i = blockIdx.x * 256 + threadIdx.x;
    if (i >= 512 * 128) return;
    int k = i >> 7, j = i & 127;
    w[i] = (k < 256) ? m2[k * 128 + j] : r2[(k - 256) * 128 + j];
}
__global__ void pack_wecat(const float* __restrict__ m1, const float* __restrict__ r1,
                           const float* __restrict__ mb1, const float* __restrict__ rb1,
                           float* __restrict__ w, float* __restrict__ bcat) {
    int i = blockIdx.x * 256 + threadIdx.x;
    if (i < 64 * 512) {
        int k = i >> 9, j = i & 511;
        w[i] = (j < 256) ? m1[(256 + k) * 256 + j] : r1[(256 + k) * 256 + (j - 256)];
    }
    if (i < 512) bcat[i] = (i < 256) ? mb1[i] : rb1[i - 256];
}

__global__ void deg_count(const int* __restrict__ fr, const int* __restrict__ to,
                          int* din, int* dout, int E) {
    int e = blockIdx.x * 256 + threadIdx.x;
    if (e < E) { atomicAdd(&din[to[e]], 1); atomicAdd(&dout[fr[e]], 1); }
}
__global__ void exscan_kernel(const int* __restrict__ in, int* __restrict__ out, int n) {
    __shared__ int buf[1024];
    __shared__ int carry_s;
    int t = threadIdx.x;
    if (t == 0) carry_s = 0;
    __syncthreads();
    for (int base = 0; base < n; base += 1024) {
        int i = base + t;
        int v = (i < n) ? in[i] : 0;
        buf[t] = v;
        __syncthreads();
        for (int d = 1; d < 1024; d <<= 1) {
            int x = (t >= d) ? buf[t - d] : 0;
            __syncthreads();
            buf[t] += x;
            __syncthreads();
        }
        if (i < n) out[i] = carry_s + buf[t] - v;
        int tot = buf[1023];
        __syncthreads();
        if (t == 0) carry_s += tot;
        __syncthreads();
    }
    if (t == 0) out[n] = carry_s;
}
__global__ void csr_fill(const int* __restrict__ fr, const int* __restrict__ to,
                         int* cin, int* cout, int* iin, int* iout, int E) {
    int e = blockIdx.x * 256 + threadIdx.x;
    if (e < E) {
        int s  = atomicAdd(&cin [to[e]], 1); iin [s]  = e;
        int s2 = atomicAdd(&cout[fr[e]], 1); iout[s2] = e;
    }
}

__global__ __launch_bounds__(256) void permute_edges(
    const float* __restrict__ eMR, const int* __restrict__ idx,
    const int* __restrict__ endp, int eoff,
    __nv_bfloat162* __restrict__ ecsr, int* __restrict__ ocsr, int E)
{
    int j = blockIdx.x * 8 + (threadIdx.x >> 5);
    if (j >= E) return;
    int lane = threadIdx.x & 31;
    int e = idx[j];
    if (lane == 0) ocsr[j] = endp[e];
    const float2* src = (const float2*)(eMR + (size_t)e * 512 + eoff);
    __nv_bfloat162* dst = ecsr + (size_t)j * 128;
    #pragma unroll
    for (int k = 0; k < 4; ++k) {
        float2 v = src[lane + 32 * k];
        dst[lane + 32 * k] = __floats2bfloat162_rn(v.x, v.y);
    }
}

__global__ __launch_bounds__(256) void agg_kernel(
    const int* __restrict__ ptr, const int* __restrict__ ocsr,
    const __nv_bfloat162* __restrict__ AB, int aoff, int boff,
    const __nv_bfloat162* __restrict__ ecsr,
    float* __restrict__ aggH, int ooff, int Nn)
{
    int n = (blockIdx.x * blockDim.x + threadIdx.x) >> 5;
    int lane = threadIdx.x & 31;
    if (n >= Nn) return;
    float bv[8], acc[8];
    const __nv_bfloat162* bp = AB + (size_t)n * 512 + boff;
    #pragma unroll
    for (int k = 0; k < 4; ++k) {
        float2 b2 = __bfloat1622float2(bp[lane + 32 * k]);
        bv[2 * k] = b2.x; bv[2 * k + 1] = b2.y;
        acc[2 * k] = 0.f; acc[2 * k + 1] = 0.f;
    }
    int s = ptr[n], e1 = ptr[n + 1];
    for (int j = s; j < e1; ++j) {
        int o = ocsr[j];
        const __nv_bfloat162* ap = AB + (size_t)o * 512 + aoff;
        const __nv_bfloat162* ep = ecsr + (size_t)j * 128;
        #pragma unroll
        for (int k = 0; k < 4; ++k) {
            float2 a2 = __bfloat1622float2(ap[lane + 32 * k]);
            float2 e2 = __bfloat1622float2(ep[lane + 32 * k]);
            acc[2 * k]     += fmaxf(a2.x + e2.x + bv[2 * k],     0.f);
            acc[2 * k + 1] += fmaxf(a2.y + e2.y + bv[2 * k + 1], 0.f);
        }
    }
    float2* op = (float2*)(aggH + (size_t)n * 512 + ooff);
    #pragma unroll
    for (int k = 0; k < 4; ++k) op[lane + 32 * k] = make_float2(acc[2 * k], acc[2 * k + 1]);
}

__global__ void biascat_kernel(float* __restrict__ cat, const float* __restrict__ h,
                               const int* __restrict__ pin, const int* __restrict__ pout,
                               const float* __restrict__ mb2, const float* __restrict__ rb2) {
    int n = blockIdx.x, t = threadIdx.x;
    if (t < 128) {
        float di = (float)(pin [n + 1] - pin [n]);
        float dz = (float)(pout[n + 1] - pout[n]);
        cat[(size_t)n * 256 + t] += di * mb2[t] + dz * rb2[t];
    } else {
        cat[(size_t)n * 256 + t] = h[(size_t)n * 128 + (t - 128)];
    }
}

__global__ void build_sizes(const int* __restrict__ qs, const int* __restrict__ cs,
                            int* __restrict__ sizes, int B2) {
    int i = blockIdx.x * 256 + threadIdx.x;
    if (i < B2) sizes[i] = (i & 1) ? cs[i >> 1] : qs[i >> 1];
}
__global__ void scatter_kernel(const float* __restrict__ h, const int* __restrict__ gidx,
                               const int* __restrict__ starts, float* __restrict__ st) {
    int n = blockIdx.x, t = threadIdx.x;
    int g = gidx[n];
    int pos = n - starts[g];
    st[((size_t)g * 128 + pos) * 128 + t] = h[(size_t)n * 128 + t];
}
__global__ void mask_kernel(float* __restrict__ tt, const int* __restrict__ qs,
                            const int* __restrict__ cs) {
    int r = blockIdx.x, j = threadIdx.x;
    int b = r >> 8, side = (r >> 7) & 1, pos = r & 127;
    int sz = side ? cs[b] : qs[b];
    if (pos >= sz) tt[(size_t)r * 128 + j] = 0.f;
}

__global__ __launch_bounds__(256) void pair_gemm_kernel(const float* __restrict__ tt,
                                                        float* __restrict__ la) {
    int b = blockIdx.x;
    const float* Aq = tt + (size_t)(2 * b)     * 16384;
    const float* Ac = tt + (size_t)(2 * b + 1) * 16384;
    __shared__ float As[16][132], Bs[16][132];
    int t = threadIdx.x, tx = t & 15, ty = t >> 4;
    float acc[8][8];
    #pragma unroll
    for (int i = 0; i < 8; ++i)
        #pragma unroll
        for (int j = 0; j < 8; ++j) acc[i][j] = 0.f;
    for (int k0 = 0; k0 < 128; k0 += 16) {
        #pragma unroll
        for (int it = 0; it < 2; ++it) {
            int m = (t >> 2) + it * 64, kq = (t & 3) * 4;
            float4 v = *(const float4*)&Aq[m * 128 + k0 + kq];
            As[kq][m] = v.x; As[kq + 1][m] = v.y; As[kq + 2][m] = v.z; As[kq + 3][m] = v.w;
            float4 w = *(const float4*)&Ac[m * 128 + k0 + kq];
            Bs[kq][m] = w.x; Bs[kq + 1][m] = w.y; Bs[kq + 2][m] = w.z; Bs[kq + 3][m] = w.w;
        }
        __syncthreads();
        #pragma unroll
        for (int k = 0; k < 16; ++k) {
            float a[8], bv[8];
            *(float4*)(a)      = *(const float4*)&As[k][ty * 8];
            *(float4*)(a + 4)  = *(const float4*)&As[k][ty * 8 + 4];
            *(float4*)(bv)     = *(const float4*)&Bs[k][tx * 8];
            *(float4*)(bv + 4) = *(const float4*)&Bs[k][tx * 8 + 4];
            #pragma unroll
            for (int i = 0; i < 8; ++i)
                #pragma unroll
                for (int j = 0; j < 8; ++j) acc[i][j] += a[i] * bv[j];
        }
        __syncthreads();
    }
    float* dst = la + (size_t)b * 16384;
    #pragma unroll
    for (int i = 0; i < 8; ++i)
        #pragma unroll
        for (int j = 0; j < 8; ++j)
            dst[(ty * 8 + i) * 128 + tx * 8 + j] = acc[i][j] * 10.0f;
}

__global__ __launch_bounds__(256) void sinkhorn_kernel(float* __restrict__ la_g) {
    extern __shared__ float la[];
    int b = blockIdx.x;
    float* src = la_g + (size_t)b * 16384;
    int t = threadIdx.x;
    for (int i = t; i < 16384; i += 256) la[(i >> 7) * 129 + (i & 127)] = src[i];
    __syncthreads();
    int warp = t >> 5, lane = t & 31;
    for (int iter = 0; iter < 20; ++iter) {
        for (int q = warp; q < 128; q += 8) {
            float v0 = la[q * 129 + lane],      v1 = la[q * 129 + lane + 32];
            float v2 = la[q * 129 + lane + 64], v3 = la[q * 129 + lane + 96];
            float m = warp_max(fmaxf(fmaxf(v0, v1), fmaxf(v2, v3)));
            float s = warp_sum(__expf(v0 - m) + __expf(v1 - m) + __expf(v2 - m) + __expf(v3 - m));
            float lse = m + __logf(s);
            la[q * 129 + lane]      = v0 - lse;
            la[q * 129 + lane + 32] = v1 - lse;
            la[q * 129 + lane + 64] = v2 - lse;
            la[q * 129 + lane + 96] = v3 - lse;
        }
        __syncthreads();
        for (int c = warp; c < 128; c += 8) {
            float v0 = la[lane * 129 + c],        v1 = la[(lane + 32) * 129 + c];
            float v2 = la[(lane + 64) * 129 + c], v3 = la[(lane + 96) * 129 + c];
            float m = warp_max(fmaxf(fmaxf(v0, v1), fmaxf(v2, v3)));
            float s = warp_sum(__expf(v0 - m) + __expf(v1 - m) + __expf(v2 - m) + __expf(v3 - m));
            float lse = m + __logf(s);
            la[lane * 129 + c]        = v0 - lse;
            la[(lane + 32) * 129 + c] = v1 - lse;
            la[(lane + 64) * 129 + c] = v2 - lse;
            la[(lane + 96) * 129 + c] = v3 - lse;
        }
        __syncthreads();
    }
    for (int i = t; i < 16384; i += 256) src[i] = __expf(la[(i >> 7) * 129 + (i & 127)]);
}

__global__ __launch_bounds__(256) void score_kernel(const float* __restrict__ plan,
                                                    const float* __restrict__ stacked,
                                                    float* __restrict__ out) {
    int b = blockIdx.x;
    const float* P  = plan    + (size_t)b * 16384;
    const float* Q  = stacked + (size_t)(2 * b)     * 16384;
    const float* Cm = stacked + (size_t)(2 * b + 1) * 16384;
    __shared__ float As[16][132], Bs[16][132];
    int t = threadIdx.x, tx = t & 15, ty = t >> 4;
    float acc[8][8];
    #pragma unroll
    for (int i = 0; i < 8; ++i)
        #pragma unroll
        for (int j = 0; j < 8; ++j) acc[i][j] = 0.f;
    for (int k0 = 0; k0 < 128; k0 += 16) {
        #pragma unroll
        for (int it = 0; it < 2; ++it) {
            int m = (t >> 2) + it * 64, kq = (t & 3) * 4;
            float4 v = *(const float4*)&P[m * 128 + k0 + kq];
            As[kq][m] = v.x; As[kq + 1][m] = v.y; As[kq + 2][m] = v.z; As[kq + 3][m] = v.w;
        }
        #pragma unroll
        for (int it = 0; it < 2; ++it) {
            int kk = (t >> 5) + it * 8, nq = (t & 31) * 4;
            *(float4*)&Bs[kk][nq] = *(const float4*)&Cm[(k0 + kk) * 128 + nq];
        }
        __syncthreads();
        #pragma unroll
        for (int k = 0; k < 16; ++k) {
            float a[8], bv[8];
            *(float4*)(a)      = *(const float4*)&As[k][ty * 8];
            *(float4*)(a + 4)  = *(const float4*)&As[k][ty * 8 + 4];
            *(float4*)(bv)     = *(const float4*)&Bs[k][tx * 8];
            *(float4*)(bv + 4) = *(const float4*)&Bs[k][tx * 8 + 4];
            #pragma unroll
            for (int i = 0; i < 8; ++i)
                #pragma unroll
                for (int j = 0; j < 8; ++j) acc[i][j] += a[i] * bv[j];
        }
        __syncthreads();
    }
    float s = 0.f;
    #pragma unroll
    for (int i = 0; i < 8; ++i)
        #pragma unroll
        for (int j = 0; j < 8; ++j)
            s += fmaxf(Q[(ty * 8 + i) * 128 + tx * 8 + j] - acc[i][j], 0.f);
    s = warp_sum(s);
    __shared__ float red[8];
    if ((t & 31) == 0) red[t >> 5] = s;
    __syncthreads();
    if (t == 0) {
        float tot = 0.f;
        #pragma unroll
        for (int i = 0; i < 8; ++i) tot += red[i];
        out[b] = -tot;
    }
}

template <typename T>
static T* sym(const void* s) { void* p = nullptr; cudaGetSymbolAddress(&p, s); return (T*)p; }

extern "C" void kernel_launch(void* const* d_in, const int* in_sizes, int n_in,
                              void* d_out, int out_size) {
    const float* nf  = (const float*)d_in[0];
    const float* ef  = (const float*)d_in[1];
    const float* enW = (const float*)d_in[2];  const float* enB = (const float*)d_in[3];
    const float* eeW = (const float*)d_in[4];  const float* eeB = (const float*)d_in[5];
    const float* m1  = (const float*)d_in[6];  const float* mb1 = (const float*)d_in[7];
    const float* m2  = (const float*)d_in[8];  const float* mb2 = (const float*)d_in[9];
    const float* r1  = (const float*)d_in[10]; const float* rb1 = (const float*)d_in[11];
    const float* r2  = (const float*)d_in[12]; const float* rb2 = (const float*)d_in[13];
    const float* u1  = (const float*)d_in[14]; const float* ub1 = (const float*)d_in[15];
    const float* u2  = (const float*)d_in[16]; const float* ub2 = (const float*)d_in[17];
    const float* f1  = (const float*)d_in[18]; const float* f1b = (const float*)d_in[19];
    const float* f2  = (const float*)d_in[20]; const float* f2b = (const float*)d_in[21];
    const int* fr  = (const int*)d_in[22];
    const int* to  = (const int*)d_in[23];
    const int* gix = (const int*)d_in[24];
    const int* qs  = (const int*)d_in[25];
    const int* cs  = (const int*)d_in[26];
    const int E  = in_sizes[22];
    const int N  = in_sizes[24];
    const int B  = in_sizes[25];
    const int B2 = 2 * B;
    float* out = (float*)d_out;

    float* h    = sym<float>(g_h);    float* eenc = sym<float>(g_eenc);
    float* eMR  = sym<float>(g_eMR);
    __nv_bfloat16* ABh = sym<__nv_bfloat16>(g_ABh);
    __nv_bfloat16* eMc = sym<__nv_bfloat16>(g_eMc);
    __nv_bfloat16* eRc = sym<__nv_bfloat16>(g_eRc);
    float* aggH = sym<float>(g_aggH); float* cat  = sym<float>(g_cat);
    float* hid  = sym<float>(g_hid);  float* tt   = sym<float>(g_t);
    float* stk  = sym<float>(g_stk);  float* la   = sym<float>(g_la);
    float* W1c  = sym<float>(g_W1cat); float* W2c = sym<float>(g_W2cat);
    float* Wec  = sym<float>(g_Wecat); float* bec = sym<float>(g_becat);
    int* sizes = sym<int>(g_sizes); int* starts = sym<int>(g_starts);
    int* din = sym<int>(g_din);   int* dout = sym<int>(g_dout);
    int* pin = sym<int>(g_pin);   int* pout = sym<int>(g_pout);
    int* cin = sym<int>(g_cin);   int* cout = sym<int>(g_cout);
    int* iin = sym<int>(g_iin);   int* iout = sym<int>(g_iout);
    int* oin = sym<int>(g_oin);   int* oout = sym<int>(g_oout);

    static bool attr_set = false;
    if (!attr_set) {
        cudaFuncSetAttribute(sinkhorn_kernel,
                             cudaFuncAttributeMaxDynamicSharedMemorySize, 128 * 129 * 4);
        attr_set = true;
    }

    // ---- launches 1-6: packing + encoders + round-0 ABp (6th = ncu capture) ----
    pack_w1cat<<<(128 * 1024 + 255) / 256, 256>>>(m1, r1, W1c);
    pack_w2cat<<<(512 * 128 + 255) / 256, 256>>>(m2, r2, W2c);
    pack_wecat<<<(64 * 512 + 255) / 256, 256>>>(m1, r1, mb1, rb1, Wec, bec);
    gemm_tf32<1, float><<<dim3(2, N / 128), 256>>>(nf, 32, enW, 128, h, 128, enB, 32);
    gemm_tf32<1, float><<<dim3(1, E / 128), 256>>>(ef, 16, eeW, 64, eenc, 64, eeB, 16);
    gemm_bf16k<0, __nv_bfloat16><<<dim3(16, N / 128), 256>>>(h, 128, W1c, 1024, ABh, 1024, nullptr, 128);

    // ---- graph structure ----
    zero_i<<<(N + 255) / 256, 256>>>(din, N);
    zero_i<<<(N + 255) / 256, 256>>>(dout, N);
    build_sizes<<<(B2 + 255) / 256, 256>>>(qs, cs, sizes, B2);
    exscan_kernel<<<1, 1024>>>(sizes, starts, B2);
    deg_count<<<(E + 255) / 256, 256>>>(fr, to, din, dout, E);
    exscan_kernel<<<1, 1024>>>(din, pin, N);
    exscan_kernel<<<1, 1024>>>(dout, pout, N);
    copy_i<<<(N + 255) / 256, 256>>>(pin, cin, N);
    copy_i<<<(N + 255) / 256, 256>>>(pout, cout, N);
    csr_fill<<<(E + 255) / 256, 256>>>(fr, to, cin, cout, iin, iout, E);

    // ---- edge-constant precompute + bf16 CSR order ----
    gemm_tf32<1, float><<<dim3(8, E / 128), 256>>>(eenc, 64, Wec, 512, eMR, 512, bec, 64);
    permute_edges<<<(E + 7) / 8, 256>>>(eMR, iin,  fr, 0,   (__nv_bfloat162*)eMc, oin,  E);
    permute_edges<<<(E + 7) / 8, 256>>>(eMR, iout, to, 256, (__nv_bfloat162*)eRc, oout, E);

    // ---- propagation rounds ----
    for (int r = 0; r < 5; ++r) {
        if (r > 0)
            gemm_bf16k<0, __nv_bfloat16><<<dim3(16, N / 128), 256>>>(h, 128, W1c, 1024, ABh, 1024, nullptr, 128);
        agg_kernel<<<(N + 7) / 8, 256>>>(pin,  oin,  (const __nv_bfloat162*)ABh, 0,   128,
                                         (const __nv_bfloat162*)eMc, aggH, 0,   N);
        agg_kernel<<<(N + 7) / 8, 256>>>(pout, oout, (const __nv_bfloat162*)ABh, 256, 384,
                                         (const __nv_bfloat162*)eRc, aggH, 256, N);
        gemm_tf32<0, float><<<dim3(2, N / 128), 256>>>(aggH, 512, W2c, 128, cat, 256, nullptr, 512);
        biascat_kernel<<<N, 256>>>(cat, h, pin, pout, mb2, rb2);
        gemm_tf32<2, float><<<dim3(4, N / 128), 256>>>(cat, 256, u1, 256, hid, 256, ub1, 256);
        gemm_tf32<3, float><<<dim3(2, N / 128), 256>>>(hid, 256, u2, 128, h, 128, ub2, 256);
    }

    // ---- stack + transform ----
    zero_f<<<2048, 256>>>(stk, (size_t)B2 * 16384);
    scatter_kernel<<<N, 128>>>(h, gix, starts, stk);
    gemm_tf32<2, float><<<dim3(2, B2), 256>>>(stk, 128, f1, 128, hid, 128, f1b, 128);
    gemm_tf32<1, float><<<dim3(2, B2), 256>>>(hid, 128, f2, 128, tt, 128, f2b, 128);
    mask_kernel<<<B2 * 128, 128>>>(tt, qs, cs);

    // ---- sinkhorn + score ----
    pair_gemm_kernel<<<B, 256>>>(tt, la);
    sinkhorn_kernel<<<B, 256, 128 * 129 * 4>>>(la);
    score_kernel<<<B, 256>>>(la, stk, out);
}

// round 10
// speedup vs baseline: 1.1218x; 1.1218x over previous
#include <cuda_runtime.h>
#include <cuda_bf16.h>
#include <cstdint>
#include <cstddef>

#define NMAX 98304
#define EMAX 786432
#define BMAX 512

__device__ float g_h   [(size_t)NMAX * 128];
__device__ float g_eenc[(size_t)EMAX * 64];
__device__ float g_eP  [(size_t)EMAX * 128];   // two E x 64 permuted eenc buffers
__device__ __nv_bfloat16 g_ABh [(size_t)NMAX * 1024];
__device__ __nv_bfloat16 g_eMc [(size_t)EMAX * 256];
__device__ __nv_bfloat16 g_eRc [(size_t)EMAX * 256];
__device__ float g_aggH[(size_t)NMAX * 512];
__device__ float g_cat [(size_t)NMAX * 256];
__device__ float g_hid [(size_t)NMAX * 256];
__device__ float g_t   [(size_t)BMAX * 2 * 128 * 128];
__device__ float g_stk [(size_t)BMAX * 2 * 128 * 128];
__device__ float g_la  [(size_t)BMAX * 128 * 128];
__device__ float g_W1cat[128 * 1024];
__device__ float g_W2cat[512 * 128];
__device__ float g_Wecat[64 * 512];
__device__ float g_becat[512];
__device__ int   g_sizes [2 * BMAX];
__device__ int   g_starts[2 * BMAX + 1];
__device__ int   g_din [NMAX];
__device__ int   g_dout[NMAX];
__device__ int   g_pin [NMAX + 1];
__device__ int   g_pout[NMAX + 1];
__device__ int   g_cin [NMAX];
__device__ int   g_cout[NMAX];
__device__ int   g_iin [EMAX];
__device__ int   g_iout[EMAX];
__device__ int   g_oin [EMAX];
__device__ int   g_oout[EMAX];

__device__ __forceinline__ float warp_max(float v) {
    #pragma unroll
    for (int o = 16; o; o >>= 1) v = fmaxf(v, __shfl_xor_sync(0xffffffffu, v, o));
    return v;
}
__device__ __forceinline__ float warp_sum(float v) {
    #pragma unroll
    for (int o = 16; o; o >>= 1) v += __shfl_xor_sync(0xffffffffu, v, o);
    return v;
}
__device__ __forceinline__ uint32_t f2tf32(float x) {
    uint32_t r;
    asm("cvt.rna.tf32.f32 %0, %1;" : "=r"(r) : "f"(x));
    return r;
}
__device__ __forceinline__ uint32_t pkbf(float x, float y) {
    __nv_bfloat162 h = __floats2bfloat162_rn(x, y);
    return *(uint32_t*)&h;
}
__device__ __forceinline__ void mma_tf32(float* d, const uint32_t* a, const uint32_t* b) {
    asm volatile(
        "mma.sync.aligned.m16n8k8.row.col.f32.tf32.tf32.f32 "
        "{%0,%1,%2,%3}, {%4,%5,%6,%7}, {%8,%9}, {%0,%1,%2,%3};"
        : "+f"(d[0]), "+f"(d[1]), "+f"(d[2]), "+f"(d[3])
        : "r"(a[0]), "r"(a[1]), "r"(a[2]), "r"(a[3]), "r"(b[0]), "r"(b[1]));
}
__device__ __forceinline__ void mma_bf16(float* d, const uint32_t* a, const uint32_t* b) {
    asm volatile(
        "mma.sync.aligned.m16n8k16.row.col.f32.bf16.bf16.f32 "
        "{%0,%1,%2,%3}, {%4,%5,%6,%7}, {%8,%9}, {%0,%1,%2,%3};"
        : "+f"(d[0]), "+f"(d[1]), "+f"(d[2]), "+f"(d[3])
        : "r"(a[0]), "r"(a[1]), "r"(a[2]), "r"(a[3]), "r"(b[0]), "r"(b[1]));
}
__device__ __forceinline__ void store2(float v0, float v1, float* p) {
    p[0] = v0; p[1] = v1;
}
__device__ __forceinline__ void store2(float v0, float v1, __nv_bfloat16* p) {
    *(__nv_bfloat162*)p = __floats2bfloat162_rn(v0, v1);
}

__global__ void zero_f(float* p, size_t n) {
    for (size_t i = (size_t)blockIdx.x * 256 + threadIdx.x; i < n;
         i += (size_t)gridDim.x * 256) p[i] = 0.f;
}
__global__ void zero_i(int* p, int n) {
    int i = blockIdx.x * 256 + threadIdx.x;
    if (i < n) p[i] = 0;
}
__global__ void copy_i(const int* a, int* b, int n) {
    int i = blockIdx.x * 256 + threadIdx.x;
    if (i < n) b[i] = a[i];
}

// ---------------------------------------------------------------------------
// tf32 tensor-core GEMM, double-buffered smem pipeline.
// ---------------------------------------------------------------------------
template <int BN, int EPI, typename OutT>
__global__ __launch_bounds__(256) void gemm_tf32(
    const float* __restrict__ A, int lda, const float* __restrict__ W, int ldb,
    OutT* __restrict__ C, int ldc, const float* __restrict__ bias, int K)
{
    constexpr int BM = 128, BK = 16;
    constexpr int WN = BN / 4;
    constexpr int NI = WN / 8;
    constexpr int NITB = (BK * BN) / 1024;
    __shared__ uint2    As2[2][2][BM][4];
    __shared__ uint32_t Bs[2][BK][BN + 8];
    const int row0 = blockIdx.y * BM, col0 = blockIdx.x * BN;
    const int t = threadIdx.x, lane = t & 31, warp = t >> 5;
    const int wm = (warp & 1) * 64;
    const int wn = (warp >> 1) * WN;
    const int g = lane >> 2, c = lane & 3;
    const int am = t >> 1, aks = t & 1;

    float acc[4][NI][4];
    #pragma unroll
    for (int mi = 0; mi < 4; ++mi)
        #pragma unroll
        for (int ni = 0; ni < NI; ++ni)
            #pragma unroll
            for (int j = 0; j < 4; ++j) acc[mi][ni][j] = 0.f;

    float4 ra0, ra1, rb[NITB];

    auto gload = [&](int k0) {
        const float* ap = &A[(size_t)(row0 + am) * lda + k0 + aks * 8];
        ra0 = *(const float4*)(ap);
        ra1 = *(const float4*)(ap + 4);
        #pragma unroll
        for (int it = 0; it < NITB; ++it) {
            int kk = t / (BN / 4) + it * (1024 / BN);
            int nq = (t % (BN / 4)) * 4;
            rb[it] = *(const float4*)&W[(size_t)(k0 + kk) * ldb + col0 + nq];
        }
    };
    auto sstore = [&](int p) {
        As2[p][aks][am][0] = make_uint2(f2tf32(ra0.x), f2tf32(ra1.x));
        As2[p][aks][am][1] = make_uint2(f2tf32(ra0.y), f2tf32(ra1.y));
        As2[p][aks][am][2] = make_uint2(f2tf32(ra0.z), f2tf32(ra1.z));
        As2[p][aks][am][3] = make_uint2(f2tf32(ra0.w), f2tf32(ra1.w));
        #pragma unroll
        for (int it = 0; it < NITB; ++it) {
            int kk = t / (BN / 4) + it * (1024 / BN);
            int nq = (t % (BN / 4)) * 4;
            uint32_t* dst = &Bs[p][kk][nq];
            dst[0] = f2tf32(rb[it].x); dst[1] = f2tf32(rb[it].y);
            dst[2] = f2tf32(rb[it].z); dst[3] = f2tf32(rb[it].w);
        }
    };
    auto scompute = [&](int p) {
        #pragma unroll
        for (int ks = 0; ks < 2; ++ks) {
            const int kb = ks * 8;
            uint32_t af[4][4];
            #pragma unroll
            for (int mi = 0; mi < 4; ++mi) {
                int m = wm + mi * 16;
                uint2 u0 = As2[p][ks][m + g][c];
                uint2 u1 = As2[p][ks][m + g + 8][c];
                af[mi][0] = u0.x; af[mi][1] = u1.x;
                af[mi][2] = u0.y; af[mi][3] = u1.y;
            }
            uint32_t bf[NI][2];
            #pragma unroll
            for (int ni = 0; ni < NI; ++ni) {
                int n = wn + ni * 8 + g;
                bf[ni][0] = Bs[p][kb + c][n];
                bf[ni][1] = Bs[p][kb + c + 4][n];
            }
            #pragma unroll
            for (int mi = 0; mi < 4; ++mi)
                #pragma unroll
                for (int ni = 0; ni < NI; ++ni)
                    mma_tf32(acc[mi][ni], af[mi], bf[ni]);
        }
    };

    gload(0);
    sstore(0);
    __syncthreads();
    int p = 0;
    for (int k0 = 0; k0 < K; k0 += BK) {
        const bool more = (k0 + BK < K);
        if (more) gload(k0 + BK);
        scompute(p);
        if (more) sstore(p ^ 1);
        __syncthreads();
        p ^= 1;
    }
    #pragma unroll
    for (int mi = 0; mi < 4; ++mi) {
        #pragma unroll
        for (int ni = 0; ni < NI; ++ni) {
            int row = row0 + wm + mi * 16 + g;
            int col = col0 + wn + ni * 8 + 2 * c;
            #pragma unroll
            for (int half = 0; half < 2; ++half) {
                int r = row + half * 8;
                float v0 = acc[mi][ni][2 * half + 0];
                float v1 = acc[mi][ni][2 * half + 1];
                if (EPI >= 1) { v0 += bias[col]; v1 += bias[col + 1]; }
                if (EPI == 2) { v0 = fmaxf(v0, 0.f); v1 = fmaxf(v1, 0.f); }
                size_t off = (size_t)r * ldc + col;
                if (EPI == 3) { C[off] += v0; C[off + 1] += v1; }
                else          store2(v0, v1, &C[off]);
            }
        }
    }
}

// ---------------------------------------------------------------------------
// bf16 m16n8k16 GEMM, double-buffered (for the ABp GEMM).
// ---------------------------------------------------------------------------
template <int BN, int EPI, typename OutT>
__global__ __launch_bounds__(256) void gemm_bf16k(
    const float* __restrict__ A, int lda, const float* __restrict__ W, int ldb,
    OutT* __restrict__ C, int ldc, const float* __restrict__ bias, int K)
{
    constexpr int BM = 128, BK = 16;
    constexpr int WN = BN / 4;
    constexpr int NI = WN / 8;
    __shared__ uint2 As2[2][BM][5];
    __shared__ uint2 Bs2[2][BN][5];
    const int row0 = blockIdx.y * BM, col0 = blockIdx.x * BN;
    const int t = threadIdx.x, lane = t & 31, warp = t >> 5;
    const int wm = (warp & 1) * 64;
    const int wn = (warp >> 1) * WN;
    const int g = lane >> 2, c = lane & 3;
    const int am = t >> 1, ah = t & 1;
    const int bc = t >> 6, bn = (t & 63) * 2;
    const bool bact = bn < BN;

    float acc[4][NI][4];
    #pragma unroll
    for (int mi = 0; mi < 4; ++mi)
        #pragma unroll
        for (int ni = 0; ni < NI; ++ni)
            #pragma unroll
            for (int j = 0; j < 4; ++j) acc[mi][ni][j] = 0.f;

    float4 ra0, ra1;
    float2 w0, w1, w2, w3;

    auto gload = [&](int k0) {
        const float* ap = &A[(size_t)(row0 + am) * lda + k0 + 4 * ah];
        ra0 = *(const float4*)(ap);
        ra1 = *(const float4*)(ap + 8);
        if (bact) {
            const float* wp = &W[(size_t)(k0 + 2 * bc) * ldb + col0 + bn];
            w0 = *(const float2*)(wp);
            w1 = *(const float2*)(wp + ldb);
            w2 = *(const float2*)(wp + 8 * (size_t)ldb);
            w3 = *(const float2*)(wp + 9 * (size_t)ldb);
        }
    };
    auto sstore = [&](int p) {
        As2[p][am][2 * ah]     = make_uint2(pkbf(ra0.x, ra0.y), pkbf(ra1.x, ra1.y));
        As2[p][am][2 * ah + 1] = make_uint2(pkbf(ra0.z, ra0.w), pkbf(ra1.z, ra1.w));
        if (bact) {
            Bs2[p][bn][bc]     = make_uint2(pkbf(w0.x, w1.x), pkbf(w2.x, w3.x));
            Bs2[p][bn + 1][bc] = make_uint2(pkbf(w0.y, w1.y), pkbf(w2.y, w3.y));
        }
    };
    auto scompute = [&](int p) {
        uint32_t af[4][4];
        #pragma unroll
        for (int mi = 0; mi < 4; ++mi) {
            int m = wm + mi * 16;
            uint2 u0 = As2[p][m + g][c];
            uint2 u1 = As2[p][m + g + 8][c];
            af[mi][0] = u0.x; af[mi][1] = u1.x;
            af[mi][2] = u0.y; af[mi][3] = u1.y;
        }
        uint32_t bf[NI][2];
        #pragma unroll
        for (int ni = 0; ni < NI; ++ni) {
            uint2 v = Bs2[p][wn + ni * 8 + g][c];
            bf[ni][0] = v.x; bf[ni][1] = v.y;
        }
        #pragma unroll
        for (int mi = 0; mi < 4; ++mi)
            #pragma unroll
            for (int ni = 0; ni < NI; ++ni)
                mma_bf16(acc[mi][ni], af[mi], bf[ni]);
    };

    gload(0);
    sstore(0);
    __syncthreads();
    int p = 0;
    for (int k0 = 0; k0 < K; k0 += BK) {
        const bool more = (k0 + BK < K);
        if (more) gload(k0 + BK);
        scompute(p);
        if (more) sstore(p ^ 1);
        __syncthreads();
        p ^= 1;
    }
    #pragma unroll
    for (int mi = 0; mi < 4; ++mi) {
        #pragma unroll
        for (int ni = 0; ni < NI; ++ni) {
            int row = row0 + wm + mi * 16 + g;
            int col = col0 + wn + ni * 8 + 2 * c;
            #pragma unroll
            for (int half = 0; half < 2; ++half) {
                int r = row + half * 8;
                float v0 = acc[mi][ni][2 * half + 0];
                float v1 = acc[mi][ni][2 * half + 1];
                if (EPI >= 1) { v0 += bias[col]; v1 += bias[col + 1]; }
                if (EPI == 2) { v0 = fmaxf(v0, 0.f); v1 = fmaxf(v1, 0.f); }
                size_t off = (size_t)r * ldc + col;
                if (EPI == 3) { C[off] += v0; C[off + 1] += v1; }
                else          store2(v0, v1, &C[off]);
            }
        }
    }
}

__global__ void pack_w1cat(const float* __restrict__ m1, const float* __restrict__ r1,
                           float* __restrict__ w) {
    int i = blockIdx.x * 256 + threadIdx.x;
    if (i >= 128 * 1024) return;
    int k = i >> 10, j = i & 1023;
    float v;
    if (j < 256)      v = m1[k * 256 + j];
    else if (j < 512) v = m1[(128 + k) * 256 + (j - 256)];
    else if (j < 768) v = r1[k * 256 + (j - 512)];
    else              v = r1[(128 + k) * 256 + (j - 768)];
    w[i] = v;
}
__global__ void pack_w2cat(const float* __restrict__ m2, const float* __restrict__ r2,
                           float* __restrict__ w) {
    int i = blockIdx.x * 256 + threadIdx.x;
    if (i >= 512 * 128) return;
    int k = i >> 7, j = i & 127;
    w[i] = (k < 256) ? m2[k * 128 + j] : r2[(k - 256) * 128 + j];
}
__global__ void pack_wecat(const float* __restrict__ m1, const float* __restrict__ r1,
                           const float* __restrict__ mb1, const float* __restrict__ rb1,
                           float* __restrict__ w, float* __restrict__ bcat) {
    int i = blockIdx.x * 256 + threadIdx.x;
    if (i < 64 * 512) {
        int k = i >> 9, j = i & 511;
        w[i] = (j < 256) ? m1[(256 + k) * 256 + j] : r1[(256 + k) * 256 + (j - 256)];
    }
    if (i < 512) bcat[i] = (i < 256) ? mb1[i] : rb1[i - 256];
}

__global__ void deg_count(const int* __restrict__ fr, const int* __restrict__ to,
                          int* din, int* dout, int E) {
    int e = blockIdx.x * 256 + threadIdx.x;
    if (e < E) { atomicAdd(&din[to[e]], 1); atomicAdd(&dout[fr[e]], 1); }
}
__global__ void exscan_kernel(const int* __restrict__ in, int* __restrict__ out, int n) {
    __shared__ int buf[1024];
    __shared__ int carry_s;
    int t = threadIdx.x;
    if (t == 0) carry_s = 0;
    __syncthreads();
    for (int base = 0; base < n; base += 1024) {
        int i = base + t;
        int v = (i < n) ? in[i] : 0;
        buf[t] = v;
        __syncthreads();
        for (int d = 1; d < 1024; d <<= 1) {
            int x = (t >= d) ? buf[t - d] : 0;
            __syncthreads();
            buf[t] += x;
            __syncthreads();
        }
        if (i < n) out[i] = carry_s + buf[t] - v;
        int tot = buf[1023];
        __syncthreads();
        if (t == 0) carry_s += tot;
        __syncthreads();
    }
    if (t == 0) out[n] = carry_s;
}
__global__ void csr_fill(const int* __restrict__ fr, const int* __restrict__ to,
                         int* cin, int* cout, int* iin, int* iout, int E) {
    int e = blockIdx.x * 256 + threadIdx.x;
    if (e < E) {
        int s  = atomicAdd(&cin [to[e]], 1); iin [s]  = e;
        int s2 = atomicAdd(&cout[fr[e]], 1); iout[s2] = e;
    }
}

__global__ __launch_bounds__(256) void permute_eenc(
    const float* __restrict__ eenc, const int* __restrict__ idx,
    const int* __restrict__ endp, float* __restrict__ out,
    int* __restrict__ ocsr, int E)
{
    int j = blockIdx.x * 8 + (threadIdx.x >> 5);
    if (j >= E) return;
    int lane = threadIdx.x & 31;
    int e = idx[j];
    if (lane == 0) ocsr[j] = endp[e];
    const float2* s2 = (const float2*)(eenc + (size_t)e * 64);
    float2* d2 = (float2*)(out + (size_t)j * 64);
    d2[lane] = s2[lane];
}

__global__ __launch_bounds__(256) void agg_kernel(
    const int* __restrict__ ptr, const int* __restrict__ ocsr,
    const __nv_bfloat162* __restrict__ AB, int aoff, int boff,
    const __nv_bfloat162* __restrict__ ecsr,
    float* __restrict__ aggH, int ooff, int Nn)
{
    int n = (blockIdx.x * blockDim.x + threadIdx.x) >> 5;
    int lane = threadIdx.x & 31;
    if (n >= Nn) return;
    float bv[8], acc[8];
    const __nv_bfloat162* bp = AB + (size_t)n * 512 + boff;
    #pragma unroll
    for (int k = 0; k < 4; ++k) {
        float2 b2 = __bfloat1622float2(bp[lane + 32 * k]);
        bv[2 * k] = b2.x; bv[2 * k + 1] = b2.y;
        acc[2 * k] = 0.f; acc[2 * k + 1] = 0.f;
    }
    int s = ptr[n], e1 = ptr[n + 1];
    for (int j = s; j < e1; ++j) {
        int o = ocsr[j];
        const __nv_bfloat162* ap = AB + (size_t)o * 512 + aoff;
        const __nv_bfloat162* ep = ecsr + (size_t)j * 128;
        #pragma unroll
        for (int k = 0; k < 4; ++k) {
            float2 a2 = __bfloat1622float2(ap[lane + 32 * k]);
            float2 e2 = __bfloat1622float2(ep[lane + 32 * k]);
            acc[2 * k]     += fmaxf(a2.x + e2.x + bv[2 * k],     0.f);
            acc[2 * k + 1] += fmaxf(a2.y + e2.y + bv[2 * k + 1], 0.f);
        }
    }
    float2* op = (float2*)(aggH + (size_t)n * 512 + ooff);
    #pragma unroll
    for (int k = 0; k < 4; ++k) op[lane + 32 * k] = make_float2(acc[2 * k], acc[2 * k + 1]);
}

__global__ void biascat_kernel(float* __restrict__ cat, const float* __restrict__ h,
                               const int* __restrict__ pin, const int* __restrict__ pout,
                               const float* __restrict__ mb2, const float* __restrict__ rb2) {
    int n = blockIdx.x, t = threadIdx.x;
    if (t < 128) {
        float di = (float)(pin [n + 1] - pin [n]);
        float dz = (float)(pout[n + 1] - pout[n]);
        cat[(size_t)n * 256 + t] += di * mb2[t] + dz * rb2[t];
    } else {
        cat[(size_t)n * 256 + t] = h[(size_t)n * 128 + (t - 128)];
    }
}

__global__ void build_sizes(const int* __restrict__ qs, const int* __restrict__ cs,
                            int* __restrict__ sizes, int B2) {
    int i = blockIdx.x * 256 + threadIdx.x;
    if (i < B2) sizes[i] = (i & 1) ? cs[i >> 1] : qs[i >> 1];
}
__global__ void scatter_kernel(const float* __restrict__ h, const int* __restrict__ gidx,
                               const int* __restrict__ starts, float* __restrict__ st) {
    int n = blockIdx.x, t = threadIdx.x;
    int g = gidx[n];
    int pos = n - starts[g];
    st[((size_t)g * 128 + pos) * 128 + t] = h[(size_t)n * 128 + t];
}
__global__ void mask_kernel(float* __restrict__ tt, const int* __restrict__ qs,
                            const int* __restrict__ cs) {
    int r = blockIdx.x, j = threadIdx.x;
    int b = r >> 8, side = (r >> 7) & 1, pos = r & 127;
    int sz = side ? cs[b] : qs[b];
    if (pos >= sz) tt[(size_t)r * 128 + j] = 0.f;
}

__global__ __launch_bounds__(256) void pair_gemm_kernel(const float* __restrict__ tt,
                                                        float* __restrict__ la) {
    int b = blockIdx.x;
    const float* Aq = tt + (size_t)(2 * b)     * 16384;
    const float* Ac = tt + (size_t)(2 * b + 1) * 16384;
    __shared__ float As[16][132], Bs[16][132];
    int t = threadIdx.x, tx = t & 15, ty = t >> 4;
    float acc[8][8];
    #pragma unroll
    for (int i = 0; i < 8; ++i)
        #pragma unroll
        for (int j = 0; j < 8; ++j) acc[i][j] = 0.f;
    for (int k0 = 0; k0 < 128; k0 += 16) {
        #pragma unroll
        for (int it = 0; it < 2; ++it) {
            int m = (t >> 2) + it * 64, kq = (t & 3) * 4;
            float4 v = *(const float4*)&Aq[m * 128 + k0 + kq];
            As[kq][m] = v.x; As[kq + 1][m] = v.y; As[kq + 2][m] = v.z; As[kq + 3][m] = v.w;
            float4 w = *(const float4*)&Ac[m * 128 + k0 + kq];
            Bs[kq][m] = w.x; Bs[kq + 1][m] = w.y; Bs[kq + 2][m] = w.z; Bs[kq + 3][m] = w.w;
        }
        __syncthreads();
        #pragma unroll
        for (int k = 0; k < 16; ++k) {
            float a[8], bv[8];
            *(float4*)(a)      = *(const float4*)&As[k][ty * 8];
            *(float4*)(a + 4)  = *(const float4*)&As[k][ty * 8 + 4];
            *(float4*)(bv)     = *(const float4*)&Bs[k][tx * 8];
            *(float4*)(bv + 4) = *(const float4*)&Bs[k][tx * 8 + 4];
            #pragma unroll
            for (int i = 0; i < 8; ++i)
                #pragma unroll
                for (int j = 0; j < 8; ++j) acc[i][j] += a[i] * bv[j];
        }
        __syncthreads();
    }
    float* dst = la + (size_t)b * 16384;
    #pragma unroll
    for (int i = 0; i < 8; ++i)
        #pragma unroll
        for (int j = 0; j < 8; ++j)
            dst[(ty * 8 + i) * 128 + tx * 8 + j] = acc[i][j] * 10.0f;
}

// ---------------------------------------------------------------------------
// Sinkhorn with duplicate-class compression. Dup row/col only exists when its
// weight (128-R / 128-C) is nonzero — a zero-weight dup would otherwise
// poison the LSE max and underflow the weighted sum to exactly 0.
// ---------------------------------------------------------------------------
__global__ __launch_bounds__(256) void sinkhorn_kernel(float* __restrict__ la_g,
                                                       const int* __restrict__ qs,
                                                       const int* __restrict__ cs) {
    extern __shared__ float P[];  // up to [129][131]
    const int b = blockIdx.x;
    const int R = qs[b], C = cs[b];
    const float wR = (float)(128 - R), wC = (float)(128 - C);
    const int RT = (R < 128) ? R + 1 : 128;   // dup row only if masked rows exist
    const int CT = (C < 128) ? C + 1 : 128;   // dup col only if masked cols exist
    float* src = la_g + (size_t)b * 16384;
    const int t = threadIdx.x;
    for (int i = t; i < RT * CT; i += 256) {
        int q = i / CT, c = i % CT;
        P[q * 131 + c] = (q < R && c < C) ? src[q * 128 + c] : 0.f;
    }
    __syncthreads();
    const int warp = t >> 5, lane = t & 31;
    for (int iter = 0; iter < 20; ++iter) {
        // row phase: LSE over columns, dup column (index C, only if present) weighted wC
        for (int q = warp; q < RT; q += 8) {
            float m = -1e30f;
            for (int c = lane; c < CT; c += 32) m = fmaxf(m, P[q * 131 + c]);
            m = warp_max(m);
            float s = 0.f;
            for (int c = lane; c < CT; c += 32) {
                float w = (c == C) ? wC : 1.f;
                s += w * __expf(P[q * 131 + c] - m);
            }
            s = warp_sum(s);
            float lse = m + __logf(s);
            for (int c = lane; c < CT; c += 32) P[q * 131 + c] -= lse;
        }
        __syncthreads();
        // col phase: LSE over rows, dup row (index R, only if present) weighted wR
        for (int c = warp; c < CT; c += 8) {
            float m = -1e30f;
            for (int q = lane; q < RT; q += 32) m = fmaxf(m, P[q * 131 + c]);
            m = warp_max(m);
            float s = 0.f;
            for (int q = lane; q < RT; q += 32) {
                float w = (q == R) ? wR : 1.f;
                s += w * __expf(P[q * 131 + c] - m);
            }
            s = warp_sum(s);
            float lse = m + __logf(s);
            for (int q = lane; q < RT; q += 32) P[q * 131 + c] -= lse;
        }
        __syncthreads();
    }
    for (int i = t; i < 16384; i += 256) {
        int q = i >> 7, c = i & 127;
        int qe = (q < R) ? q : R;
        int ce = (c < C) ? c : C;
        src[i] = __expf(P[qe * 131 + ce]);
    }
}

__global__ __launch_bounds__(256) void score_kernel(const float* __restrict__ plan,
                                                    const float* __restrict__ stacked,
                                                    float* __restrict__ out) {
    int b = blockIdx.x;
    const float* P  = plan    + (size_t)b * 16384;
    const float* Q  = stacked + (size_t)(2 * b)     * 16384;
    const float* Cm = stacked + (size_t)(2 * b + 1) * 16384;
    __shared__ float As[16][132], Bs[16][132];
    int t = threadIdx.x, tx = t & 15, ty = t >> 4;
    float acc[8][8];
    #pragma unroll
    for (int i = 0; i < 8; ++i)
        #pragma unroll
        for (int j = 0; j < 8; ++j) acc[i][j] = 0.f;
    for (int k0 = 0; k0 < 128; k0 += 16) {
        #pragma unroll
        for (int it = 0; it < 2; ++it) {
            int m = (t >> 2) + it * 64, kq = (t & 3) * 4;
            float4 v = *(const float4*)&P[m * 128 + k0 + kq];
            As[kq][m] = v.x; As[kq + 1][m] = v.y; As[kq + 2][m] = v.z; As[kq + 3][m] = v.w;
        }
        #pragma unroll
        for (int it = 0; it < 2; ++it) {
            int kk = (t >> 5) + it * 8, nq = (t & 31) * 4;
            *(float4*)&Bs[kk][nq] = *(const float4*)&Cm[(k0 + kk) * 128 + nq];
        }
        __syncthreads();
        #pragma unroll
        for (int k = 0; k < 16; ++k) {
            float a[8], bv[8];
            *(float4*)(a)      = *(const float4*)&As[k][ty * 8];
            *(float4*)(a + 4)  = *(const float4*)&As[k][ty * 8 + 4];
            *(float4*)(bv)     = *(const float4*)&Bs[k][tx * 8];
            *(float4*)(bv + 4) = *(const float4*)&Bs[k][tx * 8 + 4];
            #pragma unroll
            for (int i = 0; i < 8; ++i)
                #pragma unroll
                for (int j = 0; j < 8; ++j) acc[i][j] += a[i] * bv[j];
        }
        __syncthreads();
    }
    float s = 0.f;
    #pragma unroll
    for (int i = 0; i < 8; ++i)
        #pragma unroll
        for (int j = 0; j < 8; ++j)
            s += fmaxf(Q[(ty * 8 + i) * 128 + tx * 8 + j] - acc[i][j], 0.f);
    s = warp_sum(s);
    __shared__ float red[8];
    if ((t & 31) == 0) red[t >> 5] = s;
    __syncthreads();
    if (t == 0) {
        float tot = 0.f;
        #pragma unroll
        for (int i = 0; i < 8; ++i) tot += red[i];
        out[b] = -tot;
    }
}

template <typename T>
static T* sym(const void* s) { void* p = nullptr; cudaGetSymbolAddress(&p, s); return (T*)p; }

extern "C" void kernel_launch(void* const* d_in, const int* in_sizes, int n_in,
                              void* d_out, int out_size) {
    const float* nf  = (const float*)d_in[0];
    const float* ef  = (const float*)d_in[1];
    const float* enW = (const float*)d_in[2];  const float* enB = (const float*)d_in[3];
    const float* eeW = (const float*)d_in[4];  const float* eeB = (const float*)d_in[5];
    const float* m1  = (const float*)d_in[6];  const float* mb1 = (const float*)d_in[7];
    const float* m2  = (const float*)d_in[8];  const float* mb2 = (const float*)d_in[9];
    const float* r1  = (const float*)d_in[10]; const float* rb1 = (const float*)d_in[11];
    const float* r2  = (const float*)d_in[12]; const float* rb2 = (const float*)d_in[13];
    const float* u1  = (const float*)d_in[14]; const float* ub1 = (const float*)d_in[15];
    const float* u2  = (const float*)d_in[16]; const float* ub2 = (const float*)d_in[17];
    const float* f1  = (const float*)d_in[18]; const float* f1b = (const float*)d_in[19];
    const float* f2  = (const float*)d_in[20]; const float* f2b = (const float*)d_in[21];
    const int* fr  = (const int*)d_in[22];
    const int* to  = (const int*)d_in[23];
    const int* gix = (const int*)d_in[24];
    const int* qs  = (const int*)d_in[25];
    const int* cs  = (const int*)d_in[26];
    const int E  = in_sizes[22];
    const int N  = in_sizes[24];
    const int B  = in_sizes[25];
    const int B2 = 2 * B;
    float* out = (float*)d_out;

    float* h    = sym<float>(g_h);    float* eenc = sym<float>(g_eenc);
    float* eP   = sym<float>(g_eP);
    __nv_bfloat16* ABh = sym<__nv_bfloat16>(g_ABh);
    __nv_bfloat16* eMc = sym<__nv_bfloat16>(g_eMc);
    __nv_bfloat16* eRc = sym<__nv_bfloat16>(g_eRc);
    float* aggH = sym<float>(g_aggH); float* cat  = sym<float>(g_cat);
    float* hid  = sym<float>(g_hid);  float* tt   = sym<float>(g_t);
    float* stk  = sym<float>(g_stk);  float* la   = sym<float>(g_la);
    float* W1c  = sym<float>(g_W1cat); float* W2c = sym<float>(g_W2cat);
    float* Wec  = sym<float>(g_Wecat); float* bec = sym<float>(g_becat);
    int* sizes = sym<int>(g_sizes); int* starts = sym<int>(g_starts);
    int* din = sym<int>(g_din);   int* dout = sym<int>(g_dout);
    int* pin = sym<int>(g_pin);   int* pout = sym<int>(g_pout);
    int* cin = sym<int>(g_cin);   int* cout = sym<int>(g_cout);
    int* iin = sym<int>(g_iin);   int* iout = sym<int>(g_iout);
    int* oin = sym<int>(g_oin);   int* oout = sym<int>(g_oout);
    float* ePa = eP;
    float* ePb = eP + (size_t)EMAX * 64;

    static bool attr_set = false;
    if (!attr_set) {
        cudaFuncSetAttribute(sinkhorn_kernel,
                             cudaFuncAttributeMaxDynamicSharedMemorySize, 129 * 131 * 4);
        attr_set = true;
    }

    // ---- launches 1-6: packing + encoders + round-0 ABp (6th = ncu capture) ----
    pack_w1cat<<<(128 * 1024 + 255) / 256, 256>>>(m1, r1, W1c);
    pack_w2cat<<<(512 * 128 + 255) / 256, 256>>>(m2, r2, W2c);
    pack_wecat<<<(64 * 512 + 255) / 256, 256>>>(m1, r1, mb1, rb1, Wec, bec);
    gemm_tf32<128, 1, float><<<dim3(1, N / 128), 256>>>(nf, 32, enW, 128, h, 128, enB, 32);
    gemm_tf32<64, 1, float><<<dim3(1, E / 128), 256>>>(ef, 16, eeW, 64, eenc, 64, eeB, 16);
    gemm_bf16k<128, 0, __nv_bfloat16><<<dim3(8, N / 128), 256>>>(h, 128, W1c, 1024, ABh, 1024, nullptr, 128);

    // ---- graph structure ----
    zero_i<<<(N + 255) / 256, 256>>>(din, N);
    zero_i<<<(N + 255) / 256, 256>>>(dout, N);
    build_sizes<<<(B2 + 255) / 256, 256>>>(qs, cs, sizes, B2);
    exscan_kernel<<<1, 1024>>>(sizes, starts, B2);
    deg_count<<<(E + 255) / 256, 256>>>(fr, to, din, dout, E);
    exscan_kernel<<<1, 1024>>>(din, pin, N);
    exscan_kernel<<<1, 1024>>>(dout, pout, N);
    copy_i<<<(N + 255) / 256, 256>>>(pin, cin, N);
    copy_i<<<(N + 255) / 256, 256>>>(pout, cout, N);
    csr_fill<<<(E + 255) / 256, 256>>>(fr, to, cin, cout, iin, iout, E);

    // ---- edge constants: permute eenc first, then GEMM directly to bf16 CSR ----
    permute_eenc<<<(E + 7) / 8, 256>>>(eenc, iin,  fr, ePa, oin,  E);
    permute_eenc<<<(E + 7) / 8, 256>>>(eenc, iout, to, ePb, oout, E);
    gemm_tf32<128, 1, __nv_bfloat16><<<dim3(2, E / 128), 256>>>(
        ePa, 64, Wec, 512, eMc, 256, bec, 64);
    gemm_tf32<128, 1, __nv_bfloat16><<<dim3(2, E / 128), 256>>>(
        ePb, 64, Wec + 256, 512, eRc, 256, bec + 256, 64);

    // ---- propagation rounds (round 0's ABp already done above) ----
    for (int r = 0; r < 5; ++r) {
        if (r > 0)
            gemm_bf16k<128, 0, __nv_bfloat16><<<dim3(8, N / 128), 256>>>(h, 128, W1c, 1024, ABh, 1024, nullptr, 128);
        agg_kernel<<<(N + 7) / 8, 256>>>(pin,  oin,  (const __nv_bfloat162*)ABh, 0,   128,
                                         (const __nv_bfloat162*)eMc, aggH, 0,   N);
        agg_kernel<<<(N + 7) / 8, 256>>>(pout, oout, (const __nv_bfloat162*)ABh, 256, 384,
                                         (const __nv_bfloat162*)eRc, aggH, 256, N);
        gemm_tf32<128, 0, float><<<dim3(1, N / 128), 256>>>(aggH, 512, W2c, 128, cat, 256, nullptr, 512);
        biascat_kernel<<<N, 256>>>(cat, h, pin, pout, mb2, rb2);
        gemm_tf32<128, 2, float><<<dim3(2, N / 128), 256>>>(cat, 256, u1, 256, hid, 256, ub1, 256);
        gemm_tf32<128, 3, float><<<dim3(1, N / 128), 256>>>(hid, 256, u2, 128, h, 128, ub2, 256);
    }

    // ---- stack + transform ----
    zero_f<<<2048, 256>>>(stk, (size_t)B2 * 16384);
    scatter_kernel<<<N, 128>>>(h, gix, starts, stk);
    gemm_tf32<128, 2, float><<<dim3(1, B2 * 128 / 128), 256>>>(stk, 128, f1, 128, hid, 128, f1b, 128);
    gemm_tf32<128, 1, float><<<dim3(1, B2 * 128 / 128), 256>>>(hid, 128, f2, 128, tt, 128, f2b, 128);
    mask_kernel<<<B2 * 128, 128>>>(tt, qs, cs);

    // ---- sinkhorn + score ----
    pair_gemm_kernel<<<B, 256>>>(tt, la);
    sinkhorn_kernel<<<B, 256, 129 * 131 * 4>>>(la, qs, cs);
    score_kernel<<<B, 256>>>(la, stk, out);
}